// round 4
// baseline (speedup 1.0000x reference)
#include <cuda_runtime.h>
#include <math.h>

// Shape fixed by reference: x,y = [16, 3, 512, 512] f32
#define BATCH   16
#define HDIM    512
#define WDIM    512
#define RSTRIP  32                    // output rows per block
#define STRIPS  (HDIM / RSTRIP)       // 16
#define NBLOCKS (BATCH * STRIPS)      // 256
#define ROWSIN  (RSTRIP + 6)          // 38 input rows incl. halo
#define RGROUPS 2                     // row-groups per block
#define THREADS (RGROUPS * 128)       // 256
#define CHUNKS  ((ROWSIN + RGROUPS - 1) / RGROUPS)  // 19
#define EPSV    1e-6f

__device__ float        g_partials[NBLOCKS];
__device__ unsigned int g_count;     // zero-init at load; reset by last block

__device__ __forceinline__ void rg_barrier(int rg) {
    asm volatile("bar.sync %0, %1;" :: "r"(rg + 1), "r"(128) : "memory");
}

struct Pipe {                          // one pipelined chunk of raw loads
    float4 a0, a1, a2, q0, q1, q2;
    bool   valid;
};

__device__ __forceinline__ void issue_loads(
    Pipe& p, const float* __restrict__ xb, const float* __restrict__ yb,
    int idx, int h0, int col0, size_t plane)
{
    const int r = h0 - 3 + idx;
    p.valid = (idx < ROWSIN) && (r >= 0) && (r < HDIM);
    if (p.valid) {
        const float* xp = xb + (size_t)r * WDIM + col0;
        const float* yp = yb + (size_t)r * WDIM + col0;
        p.a0 = *(const float4*)(xp);
        p.a1 = *(const float4*)(xp + plane);
        p.a2 = *(const float4*)(xp + 2 * plane);
        p.q0 = *(const float4*)(yp);
        p.q1 = *(const float4*)(yp + plane);
        p.q2 = *(const float4*)(yp + 2 * plane);
    }
}

__global__ __launch_bounds__(THREADS, 2) void charb_kernel(
    const float* __restrict__ x, const float* __restrict__ y,
    float* __restrict__ out)
{
    __shared__ float drow[RGROUPS][520]; // per-row-group diff row, halo-padded
    __shared__ float hs[16][WDIM];       // ring of horizontal 7-tap sums
    __shared__ float warpsum[THREADS / 32];
    __shared__ bool  isLast;

    const int tid  = threadIdx.x;
    const int rg   = tid >> 7;         // row-group 0..1
    const int c4   = tid & 127;        // float4 column index
    const int col0 = c4 << 2;

    const int blk = blockIdx.x;
    const int b   = blk / STRIPS;
    const int s   = blk % STRIPS;
    const int h0  = s * RSTRIP;

    if (c4 == 0) {                     // zero side halos once
        drow[rg][0] = drow[rg][1] = drow[rg][2] = drow[rg][3] = 0.f;
        drow[rg][516] = drow[rg][517] = drow[rg][518] = drow[rg][519] = 0.f;
    }

    const size_t plane = (size_t)HDIM * WDIM;
    const float* xb = x + (size_t)b * 3 * plane;
    const float* yb = y + (size_t)b * 3 * plane;

    float acc = 0.f;
    Pipe A, B;
    issue_loads(A, xb, yb, 0 * RGROUPS + rg, h0, col0, plane);   // chunk 0
    issue_loads(B, xb, yb, 1 * RGROUPS + rg, h0, col0, plane);   // chunk 1

    #pragma unroll 1
    for (int ch = 0; ch < CHUNKS; ch += 2) {
        // ---------- even half: consume A, refill A with ch+2 ----------
        {
            const int idx = ch * RGROUPS + rg;
            float4 d = make_float4(0.f, 0.f, 0.f, 0.f);
            if (A.valid) {
                d.x = (A.a0.x - A.q0.x) + (A.a1.x - A.q1.x) + (A.a2.x - A.q2.x);
                d.y = (A.a0.y - A.q0.y) + (A.a1.y - A.q1.y) + (A.a2.y - A.q2.y);
                d.z = (A.a0.z - A.q0.z) + (A.a1.z - A.q1.z) + (A.a2.z - A.q2.z);
                d.w = (A.a0.w - A.q0.w) + (A.a1.w - A.q1.w) + (A.a2.w - A.q2.w);
            }
            *(float4*)&drow[rg][4 + col0] = d;

            issue_loads(A, xb, yb, (ch + 2) * RGROUPS + rg, h0, col0, plane);

            rg_barrier(rg);

            float f[12];
            *(float4*)&f[0] = *(const float4*)&drow[rg][col0];
            *(float4*)&f[4] = *(const float4*)&drow[rg][col0 + 4];
            *(float4*)&f[8] = *(const float4*)&drow[rg][col0 + 8];
            const float s0 = ((f[1] + f[2]) + (f[3] + f[4])) + ((f[5] + f[6]) + f[7]);
            const float s1 = s0 - f[1] + f[8];
            const float s2 = s1 - f[2] + f[9];
            const float s3 = s2 - f[3] + f[10];
            *(float4*)&hs[idx & 15][col0] = make_float4(s0, s1, s2, s3);

            __syncthreads();

            const int o = idx - 6;
            if (o >= 0 && o < RSTRIP) {
                float4 v = *(const float4*)&hs[o & 15][col0];
                #pragma unroll
                for (int t = 1; t < 7; ++t) {
                    const float4 hv = *(const float4*)&hs[(o + t) & 15][col0];
                    v.x += hv.x; v.y += hv.y; v.z += hv.z; v.w += hv.w;
                }
                const float inv = 1.f / 49.f;
                v.x *= inv; v.y *= inv; v.z *= inv; v.w *= inv;
                acc += (sqrtf(v.x * v.x + EPSV) + sqrtf(v.y * v.y + EPSV))
                     + (sqrtf(v.z * v.z + EPSV) + sqrtf(v.w * v.w + EPSV));
            }
        }

        // ---------- odd half: consume B, refill B with ch+3 ----------
        if (ch + 1 < CHUNKS) {
            const int idx = (ch + 1) * RGROUPS + rg;
            float4 d = make_float4(0.f, 0.f, 0.f, 0.f);
            if (B.valid) {
                d.x = (B.a0.x - B.q0.x) + (B.a1.x - B.q1.x) + (B.a2.x - B.q2.x);
                d.y = (B.a0.y - B.q0.y) + (B.a1.y - B.q1.y) + (B.a2.y - B.q2.y);
                d.z = (B.a0.z - B.q0.z) + (B.a1.z - B.q1.z) + (B.a2.z - B.q2.z);
                d.w = (B.a0.w - B.q0.w) + (B.a1.w - B.q1.w) + (B.a2.w - B.q2.w);
            }
            *(float4*)&drow[rg][4 + col0] = d;

            issue_loads(B, xb, yb, (ch + 3) * RGROUPS + rg, h0, col0, plane);

            rg_barrier(rg);

            float f[12];
            *(float4*)&f[0] = *(const float4*)&drow[rg][col0];
            *(float4*)&f[4] = *(const float4*)&drow[rg][col0 + 4];
            *(float4*)&f[8] = *(const float4*)&drow[rg][col0 + 8];
            const float s0 = ((f[1] + f[2]) + (f[3] + f[4])) + ((f[5] + f[6]) + f[7]);
            const float s1 = s0 - f[1] + f[8];
            const float s2 = s1 - f[2] + f[9];
            const float s3 = s2 - f[3] + f[10];
            *(float4*)&hs[idx & 15][col0] = make_float4(s0, s1, s2, s3);

            __syncthreads();

            const int o = idx - 6;
            if (o >= 0 && o < RSTRIP) {
                float4 v = *(const float4*)&hs[o & 15][col0];
                #pragma unroll
                for (int t = 1; t < 7; ++t) {
                    const float4 hv = *(const float4*)&hs[(o + t) & 15][col0];
                    v.x += hv.x; v.y += hv.y; v.z += hv.z; v.w += hv.w;
                }
                const float inv = 1.f / 49.f;
                v.x *= inv; v.y *= inv; v.z *= inv; v.w *= inv;
                acc += (sqrtf(v.x * v.x + EPSV) + sqrtf(v.y * v.y + EPSV))
                     + (sqrtf(v.z * v.z + EPSV) + sqrtf(v.w * v.w + EPSV));
            }
        }
    }

    // block reduction
    #pragma unroll
    for (int off = 16; off; off >>= 1) acc += __shfl_xor_sync(0xffffffffu, acc, off);
    if ((tid & 31) == 0) warpsum[tid >> 5] = acc;
    __syncthreads();
    if (tid < 32) {
        float v = (tid < THREADS / 32) ? warpsum[tid] : 0.f;
        #pragma unroll
        for (int off = 8; off; off >>= 1) v += __shfl_xor_sync(0xffffffffu, v, off);
        if (tid == 0) {
            g_partials[blk] = v;
            __threadfence();
            const unsigned int t = atomicAdd(&g_count, 1u);
            isLast = (t == NBLOCKS - 1);
        }
    }
    __syncthreads();

    // last-arriving block folds the 256 partials -> scalar
    if (isLast) {
        __threadfence();
        float v = (tid < NBLOCKS) ? g_partials[tid] : 0.f;
        #pragma unroll
        for (int off = 16; off; off >>= 1) v += __shfl_xor_sync(0xffffffffu, v, off);
        if ((tid & 31) == 0) warpsum[tid >> 5] = v;
        __syncthreads();
        if (tid < 32) {
            float v2 = (tid < THREADS / 32) ? warpsum[tid] : 0.f;
            #pragma unroll
            for (int off = 8; off; off >>= 1) v2 += __shfl_xor_sync(0xffffffffu, v2, off);
            if (tid == 0) {
                out[0]  = v2 / (float)((size_t)BATCH * HDIM * WDIM);
                g_count = 0u;
            }
        }
    }
}

extern "C" void kernel_launch(void* const* d_in, const int* in_sizes, int n_in,
                              void* d_out, int out_size)
{
    (void)in_sizes; (void)n_in; (void)out_size;
    const float* x = (const float*)d_in[0];
    const float* y = (const float*)d_in[1];
    float* out = (float*)d_out;

    charb_kernel<<<NBLOCKS, THREADS>>>(x, y, out);
}